// round 8
// baseline (speedup 1.0000x reference)
#include <cuda_runtime.h>
#include <cstdint>
#include <math.h>

#define BB  8
#define TT  2048
#define CC  1024
#define DKH 64
#define BT  (BB*TT)   // 16384

// tf32-rounded intermediates (Q pre-scaled by dk^-0.5; V stored transposed per batch)
__device__ __align__(256) float g_Q[BT*DKH];
__device__ __align__(256) float g_K[BT*DKH];
__device__ __align__(256) float g_Vt[BB*DKH*TT];

// ---------------------------------------------------------------------------
// helpers
// ---------------------------------------------------------------------------
__device__ __forceinline__ uint32_t smem_u32(const void* p) {
    uint32_t a;
    asm("{ .reg .u64 t; cvta.to.shared.u64 t, %1; cvt.u32.u64 %0, t; }" : "=r"(a) : "l"(p));
    return a;
}
__device__ __forceinline__ void cpa16(uint32_t s, const void* g) {
    asm volatile("cp.async.cg.shared.global [%0], [%1], 16;" :: "r"(s), "l"(g));
}
#define CP_COMMIT() asm volatile("cp.async.commit_group;" ::: "memory")
#define CP_WAIT0()  asm volatile("cp.async.wait_group 0;"  ::: "memory")

// cvt.rna.tf32.f32 requires a .b32 destination register — "=r", not "=f".
__device__ __forceinline__ float rna(float x) {
    uint32_t y; asm("cvt.rna.tf32.f32 %0, %1;" : "=r"(y) : "f"(x));
    return __uint_as_float(y);
}

// m16n8k8 tf32 mma, D += A*B.  A row-major 16x8, B col-major 8x8 (k x n).
// Fragment layout (g = lane>>2, t = lane&3):
//   a0:(g,t) a1:(g+8,t) a2:(g,t+4) a3:(g+8,t+4)
//   b0:(k=t,n=g) b1:(k=t+4,n=g)
//   c0:(g,2t) c1:(g,2t+1) c2:(g+8,2t) c3:(g+8,2t+1)
__device__ __forceinline__ void mma8(float* d, const uint32_t* a, const uint32_t* b) {
    asm volatile("mma.sync.aligned.m16n8k8.row.col.f32.tf32.tf32.f32 "
        "{%0,%1,%2,%3}, {%4,%5,%6,%7}, {%8,%9}, {%0,%1,%2,%3};"
        : "+f"(d[0]), "+f"(d[1]), "+f"(d[2]), "+f"(d[3])
        : "r"(a[0]), "r"(a[1]), "r"(a[2]), "r"(a[3]), "r"(b[0]), "r"(b[1]));
}

// ---------------------------------------------------------------------------
// Kernel 1: QKV projection.  grid (128, 3), block 256 (8 warps).
// CTA: 128 rows x 64 cols of one of Q/K/V.  Warp tile 16x64 (1m x 8n).
// K staged in 32-wide chunks, register-staged LDG -> rna -> STS double buffer.
// ---------------------------------------------------------------------------
__global__ __launch_bounds__(256) void qkv_mma(
    const float* __restrict__ x, const float* __restrict__ Wq,
    const float* __restrict__ Wk, const float* __restrict__ Wv)
{
    extern __shared__ float sm[];
    float* As = sm;             // [2][128][36]
    float* Bs = sm + 2*128*36;  // [2][32][68]

    const int tid = threadIdx.x, lane = tid & 31, wid = tid >> 5;
    const int g = lane >> 2, tg = lane & 3;
    const int row0 = blockIdx.x * 128;
    const float* W = (blockIdx.y == 0) ? Wq : (blockIdx.y == 1) ? Wk : Wv;

    float acc[8][4];
    #pragma unroll
    for (int nt = 0; nt < 8; nt++)
        #pragma unroll
        for (int i = 0; i < 4; i++) acc[nt][i] = 0.f;

    float4 ax[4], bx4[2];
    // prologue: load + store chunk 0
    #pragma unroll
    for (int j = 0; j < 4; j++) { int u = tid + 256*j; int r = u >> 3, c = (u & 7) * 4;
        ax[j] = *(const float4*)(x + (size_t)(row0 + r) * CC + c); }
    #pragma unroll
    for (int j = 0; j < 2; j++) { int u = tid + 256*j; int r = u >> 4, c = (u & 15) * 4;
        bx4[j] = *(const float4*)(W + (size_t)r * DKH + c); }
    #pragma unroll
    for (int j = 0; j < 4; j++) { int u = tid + 256*j; int r = u >> 3, c = (u & 7) * 4;
        float4 w = make_float4(rna(ax[j].x), rna(ax[j].y), rna(ax[j].z), rna(ax[j].w));
        *(float4*)(As + r*36 + c) = w; }
    #pragma unroll
    for (int j = 0; j < 2; j++) { int u = tid + 256*j; int r = u >> 4, c = (u & 15) * 4;
        float4 w = make_float4(rna(bx4[j].x), rna(bx4[j].y), rna(bx4[j].z), rna(bx4[j].w));
        *(float4*)(Bs + r*68 + c) = w; }
    __syncthreads();

    for (int cc = 0; cc < 32; cc++) {
        const int buf = cc & 1;
        if (cc + 1 < 32) {   // prefetch next chunk into registers
            const int k0 = (cc + 1) * 32;
            #pragma unroll
            for (int j = 0; j < 4; j++) { int u = tid + 256*j; int r = u >> 3, c = (u & 7) * 4;
                ax[j] = *(const float4*)(x + (size_t)(row0 + r) * CC + k0 + c); }
            #pragma unroll
            for (int j = 0; j < 2; j++) { int u = tid + 256*j; int r = u >> 4, c = (u & 15) * 4;
                bx4[j] = *(const float4*)(W + (size_t)(k0 + r) * DKH + c); }
        }
        const float* A = As + buf * (128*36);
        const float* B = Bs + buf * (32*68);
        const int r = wid*16 + g;
        #pragma unroll
        for (int ks = 0; ks < 4; ks++) {
            uint32_t af[4];
            af[0] = __float_as_uint(A[r*36     + ks*8 + tg]);
            af[1] = __float_as_uint(A[(r+8)*36 + ks*8 + tg]);
            af[2] = __float_as_uint(A[r*36     + ks*8 + tg + 4]);
            af[3] = __float_as_uint(A[(r+8)*36 + ks*8 + tg + 4]);
            #pragma unroll
            for (int nt = 0; nt < 8; nt++) {
                uint32_t bf[2];
                bf[0] = __float_as_uint(B[(ks*8 + tg)*68     + nt*8 + g]);
                bf[1] = __float_as_uint(B[(ks*8 + tg + 4)*68 + nt*8 + g]);
                mma8(acc[nt], af, bf);
            }
        }
        if (cc + 1 < 32) {   // store staged regs to the other buffer
            float* Ad = As + (buf ^ 1) * (128*36);
            float* Bd = Bs + (buf ^ 1) * (32*68);
            #pragma unroll
            for (int j = 0; j < 4; j++) { int u = tid + 256*j; int r2 = u >> 3, c = (u & 7) * 4;
                float4 w = make_float4(rna(ax[j].x), rna(ax[j].y), rna(ax[j].z), rna(ax[j].w));
                *(float4*)(Ad + r2*36 + c) = w; }
            #pragma unroll
            for (int j = 0; j < 2; j++) { int u = tid + 256*j; int r2 = u >> 4, c = (u & 15) * 4;
                float4 w = make_float4(rna(bx4[j].x), rna(bx4[j].y), rna(bx4[j].z), rna(bx4[j].w));
                *(float4*)(Bd + r2*68 + c) = w; }
        }
        __syncthreads();
    }

    // epilogue
    const int yb = blockIdx.y;
    const float sc = (yb == 0) ? 0.125f : 1.0f;
    const int r = wid*16 + g;
    #pragma unroll
    for (int nt = 0; nt < 8; nt++) {
        const int col = nt*8 + 2*tg;
        if (yb < 2) {
            float* dst = (yb == 0) ? g_Q : g_K;
            *(float2*)(dst + (size_t)(row0 + r) * DKH + col) =
                make_float2(rna(acc[nt][0]*sc), rna(acc[nt][1]*sc));
            *(float2*)(dst + (size_t)(row0 + r + 8) * DKH + col) =
                make_float2(rna(acc[nt][2]*sc), rna(acc[nt][3]*sc));
        } else {
            const int gt = row0 + r;
            const int bb = gt >> 11, t0 = gt & 2047;
            g_Vt[((size_t)bb*DKH + col    ) * TT + t0    ] = rna(acc[nt][0]);
            g_Vt[((size_t)bb*DKH + col + 1) * TT + t0    ] = rna(acc[nt][1]);
            g_Vt[((size_t)bb*DKH + col    ) * TT + t0 + 8] = rna(acc[nt][2]);
            g_Vt[((size_t)bb*DKH + col + 1) * TT + t0 + 8] = rna(acc[nt][3]);
        }
    }
}

// ---------------------------------------------------------------------------
// Kernel 2: attention.  grid (16, 8), block 256 (8 warps, 16 q-rows each).
// 16 KV tiles of 128.  S computed in two 64-col halves; exp -> P (per-warp
// private smem bounce) -> PV accumulating O in registers.  K/V double-buffered
// via cp.async prefetched one tile ahead.  No max-subtraction (clamp +/-60).
// ---------------------------------------------------------------------------
__global__ __launch_bounds__(256) void attn_mma(float* __restrict__ out)
{
    extern __shared__ float sm[];
    float* Qs = sm;                     // [128][68]
    float* Ks = sm + 8704;              // [2][128][68]
    float* Vs = sm + 8704 + 2*8704;     // [2][64][132]
    float* Pp = sm + 26112 + 2*8448;    // [128][68]
    const uint32_t sb = smem_u32(sm);

    const int tid = threadIdx.x, lane = tid & 31, wid = tid >> 5;
    const int g = lane >> 2, tg = lane & 3;
    const int b  = blockIdx.y;
    const int q0 = blockIdx.x * 128;

    const float* Qg = g_Q + ((size_t)b * TT + q0) * DKH;
    const float* Kg = g_K + (size_t)b * TT * DKH;
    const float* Vg = g_Vt + (size_t)b * DKH * TT;

    // prologue: Q + K/V tile 0  (256 threads, 8 float4 each per tensor)
    #pragma unroll
    for (int j = 0; j < 8; j++) {
        int u = tid + 256*j;
        int r = u >> 4, c = (u & 15) * 4;                    // 128 x 64
        cpa16(sb + (0     + r*68 + c) * 4, Qg + (size_t)r * DKH + c);
        cpa16(sb + (8704  + r*68 + c) * 4, Kg + (size_t)r * DKH + c);
        int rv = u >> 5, cv = (u & 31) * 4;                  // 64 x 128
        cpa16(sb + (26112 + rv*132 + cv) * 4, Vg + (size_t)rv * TT + cv);
    }
    CP_COMMIT();

    float oacc[8][4];
    #pragma unroll
    for (int nt = 0; nt < 8; nt++)
        #pragma unroll
        for (int i = 0; i < 4; i++) oacc[nt][i] = 0.f;
    float l[2] = {0.f, 0.f};

    const int r = wid*16 + g;   // this thread's q-rows: r and r+8

    for (int t = 0; t < 16; t++) {
        const int buf = t & 1;
        CP_WAIT0();
        __syncthreads();

        if (t + 1 < 16) {    // prefetch next K/V tile
            const int nb = (t + 1) & 1, kt = (t + 1) * 128;
            #pragma unroll
            for (int j = 0; j < 8; j++) {
                int u = tid + 256*j;
                int rr = u >> 4, c = (u & 15) * 4;
                cpa16(sb + (8704 + nb*8704 + rr*68 + c) * 4,
                      Kg + (size_t)(kt + rr) * DKH + c);
                int rv = u >> 5, cv = (u & 31) * 4;
                cpa16(sb + (26112 + nb*8448 + rv*132 + cv) * 4,
                      Vg + (size_t)rv * TT + kt + cv);
            }
            CP_COMMIT();
        }

        const float* K = Ks + buf * 8704;
        const float* V = Vs + buf * 8448;

        #pragma unroll
        for (int h = 0; h < 2; h++) {          // two 64-key halves
            // ---- S = Q * K^T (this half) ----
            float sacc[8][4];
            #pragma unroll
            for (int nt = 0; nt < 8; nt++)
                #pragma unroll
                for (int i = 0; i < 4; i++) sacc[nt][i] = 0.f;

            #pragma unroll
            for (int ks = 0; ks < 8; ks++) {
                uint32_t af[4];
                af[0] = __float_as_uint(Qs[r*68     + ks*8 + tg]);
                af[1] = __float_as_uint(Qs[(r+8)*68 + ks*8 + tg]);
                af[2] = __float_as_uint(Qs[r*68     + ks*8 + tg + 4]);
                af[3] = __float_as_uint(Qs[(r+8)*68 + ks*8 + tg + 4]);
                #pragma unroll
                for (int nt = 0; nt < 8; nt++) {
                    int srow = h*64 + nt*8 + g;
                    uint32_t bf[2];
                    bf[0] = __float_as_uint(K[srow*68 + ks*8 + tg]);
                    bf[1] = __float_as_uint(K[srow*68 + ks*8 + tg + 4]);
                    mma8(sacc[nt], af, bf);
                }
            }

            // ---- exp + l + P store (per-warp private rows) ----
            #pragma unroll
            for (int nt = 0; nt < 8; nt++) {
                float p0 = rna(__expf(fminf(fmaxf(sacc[nt][0], -60.f), 60.f)));
                float p1 = rna(__expf(fminf(fmaxf(sacc[nt][1], -60.f), 60.f)));
                float p2 = rna(__expf(fminf(fmaxf(sacc[nt][2], -60.f), 60.f)));
                float p3 = rna(__expf(fminf(fmaxf(sacc[nt][3], -60.f), 60.f)));
                l[0] += p0 + p1;
                l[1] += p2 + p3;
                *(float2*)(Pp + r*68     + nt*8 + 2*tg) = make_float2(p0, p1);
                *(float2*)(Pp + (r+8)*68 + nt*8 + 2*tg) = make_float2(p2, p3);
            }
            __syncwarp();

            // ---- O += P * V^T (this half) ----
            #pragma unroll
            for (int ks = 0; ks < 8; ks++) {
                uint32_t af[4];
                af[0] = __float_as_uint(Pp[r*68     + ks*8 + tg]);
                af[1] = __float_as_uint(Pp[(r+8)*68 + ks*8 + tg]);
                af[2] = __float_as_uint(Pp[r*68     + ks*8 + tg + 4]);
                af[3] = __float_as_uint(Pp[(r+8)*68 + ks*8 + tg + 4]);
                #pragma unroll
                for (int nt = 0; nt < 8; nt++) {
                    int drow = nt*8 + g;
                    uint32_t bf[2];
                    bf[0] = __float_as_uint(V[drow*132 + h*64 + ks*8 + tg]);
                    bf[1] = __float_as_uint(V[drow*132 + h*64 + ks*8 + tg + 4]);
                    mma8(oacc[nt], af, bf);
                }
            }
            __syncwarp();   // all lanes done reading P before next half rewrites it
        }
    }

    // epilogue: reduce l across the 4-lane tg group, normalize, store
    #pragma unroll
    for (int i = 0; i < 2; i++) {
        l[i] += __shfl_xor_sync(0xffffffffu, l[i], 1);
        l[i] += __shfl_xor_sync(0xffffffffu, l[i], 2);
        l[i] = 1.f / l[i];
    }
    float* og = out + ((size_t)b * TT + q0) * DKH;
    #pragma unroll
    for (int nt = 0; nt < 8; nt++) {
        const int d = nt*8 + 2*tg;
        *(float2*)(og + (size_t)r * DKH + d) =
            make_float2(oacc[nt][0]*l[0], oacc[nt][1]*l[0]);
        *(float2*)(og + (size_t)(r + 8) * DKH + d) =
            make_float2(oacc[nt][2]*l[1], oacc[nt][3]*l[1]);
    }
}

// ---------------------------------------------------------------------------
extern "C" void kernel_launch(void* const* d_in, const int* in_sizes, int n_in,
                              void* d_out, int out_size)
{
    (void)in_sizes; (void)n_in; (void)out_size;
    const float* x  = (const float*)d_in[0];
    const float* Wq = (const float*)d_in[1];
    const float* Wk = (const float*)d_in[2];
    const float* Wv = (const float*)d_in[3];
    float* out = (float*)d_out;

    const int smem_qkv  = (2*128*36 + 2*32*68) * 4;            // 54,272 B
    const int smem_attn = (8704 + 2*8704 + 2*8448 + 8704) * 4; // 206,848 B

    cudaFuncSetAttribute(qkv_mma,  cudaFuncAttributeMaxDynamicSharedMemorySize, smem_qkv);
    cudaFuncSetAttribute(attn_mma, cudaFuncAttributeMaxDynamicSharedMemorySize, smem_attn);

    qkv_mma<<<dim3(BT/128, 3), 256, smem_qkv>>>(x, Wq, Wk, Wv);
    attn_mma<<<dim3(TT/128, BB), 256, smem_attn>>>(out);
}

// round 9
// speedup vs baseline: 1.1705x; 1.1705x over previous
#include <cuda_runtime.h>
#include <cstdint>
#include <math.h>

#define BB  8
#define TT  2048
#define CC  1024
#define DKH 64
#define BT  (BB*TT)   // 16384

// tf32-rounded intermediates, PAIR-PERMUTED layouts:
//  g_Q/g_K: within each 8-wide d-group, element d stored at phys (d<4 ? 2d : 2d-7)
//  g_Vt:    [b][d][key], keys pair-permuted the same way within 8-groups
// Q pre-scaled by dk^-0.5.
__device__ __align__(256) float g_Q[BT*DKH];
__device__ __align__(256) float g_K[BT*DKH];
__device__ __align__(256) float g_Vt[BB*DKH*TT];

// ---------------------------------------------------------------------------
// helpers
// ---------------------------------------------------------------------------
__device__ __forceinline__ uint32_t smem_u32(const void* p) {
    uint32_t a;
    asm("{ .reg .u64 t; cvta.to.shared.u64 t, %1; cvt.u32.u64 %0, t; }" : "=r"(a) : "l"(p));
    return a;
}
__device__ __forceinline__ void cpa16(uint32_t s, const void* g) {
    asm volatile("cp.async.cg.shared.global [%0], [%1], 16;" :: "r"(s), "l"(g));
}
#define CP_COMMIT() asm volatile("cp.async.commit_group;" ::: "memory")
#define CP_WAIT0()  asm volatile("cp.async.wait_group 0;"  ::: "memory")

// cvt.rna.tf32.f32 requires a .b32 destination register — "=r", not "=f".
__device__ __forceinline__ float rna(float x) {
    uint32_t y; asm("cvt.rna.tf32.f32 %0, %1;" : "=r"(y) : "f"(x));
    return __uint_as_float(y);
}
// pair-permutation within an 8-group: 0,4,1,5,2,6,3,7
__device__ __forceinline__ int pp(int cc) { return (cc < 4) ? 2*cc : 2*cc - 7; }

// m16n8k8 tf32 mma, D += A*B.  Fragment layout (g = lane>>2, tg = lane&3):
//   a0:(g,k=tg) a1:(g+8,tg) a2:(g,tg+4) a3:(g+8,tg+4)
//   b0:(k=tg,n=g) b1:(k=tg+4,n=g)
//   c0:(g,2tg) c1:(g,2tg+1) c2:(g+8,2tg) c3:(g+8,2tg+1)
__device__ __forceinline__ void mma8(float* d, const uint32_t* a, const uint32_t* b) {
    asm volatile("mma.sync.aligned.m16n8k8.row.col.f32.tf32.tf32.f32 "
        "{%0,%1,%2,%3}, {%4,%5,%6,%7}, {%8,%9}, {%0,%1,%2,%3};"
        : "+f"(d[0]), "+f"(d[1]), "+f"(d[2]), "+f"(d[3])
        : "r"(a[0]), "r"(a[1]), "r"(a[2]), "r"(a[3]), "r"(b[0]), "r"(b[1]));
}

// ---------------------------------------------------------------------------
// Kernel 1: QKV projection.  grid (128, 3), block 128 (4 warps) — the
// measured-good R7 config.  Warp tile 32x64 (2m x 8n).  Outputs written in
// pair-permuted layouts (see globals above).
// ---------------------------------------------------------------------------
__global__ __launch_bounds__(128) void qkv_mma(
    const float* __restrict__ x, const float* __restrict__ Wq,
    const float* __restrict__ Wk, const float* __restrict__ Wv)
{
    extern __shared__ float sm[];
    float* As = sm;             // [2][128][36]
    float* Bs = sm + 2*128*36;  // [2][32][68]

    const int tid = threadIdx.x, lane = tid & 31, wid = tid >> 5;
    const int g = lane >> 2, tg = lane & 3;
    const int row0 = blockIdx.x * 128;
    const float* W = (blockIdx.y == 0) ? Wq : (blockIdx.y == 1) ? Wk : Wv;

    float acc[2][8][4];
    #pragma unroll
    for (int mt = 0; mt < 2; mt++)
        #pragma unroll
        for (int nt = 0; nt < 8; nt++)
            #pragma unroll
            for (int i = 0; i < 4; i++) acc[mt][nt][i] = 0.f;

    float4 ax[8], bx[4];
    #pragma unroll
    for (int j = 0; j < 8; j++) { int u = tid + 128*j; int r = u >> 3, c = (u & 7) * 4;
        ax[j] = *(const float4*)(x + (size_t)(row0 + r) * CC + c); }
    #pragma unroll
    for (int j = 0; j < 4; j++) { int u = tid + 128*j; int r = u >> 4, c = (u & 15) * 4;
        bx[j] = *(const float4*)(W + (size_t)r * DKH + c); }
    #pragma unroll
    for (int j = 0; j < 8; j++) { int u = tid + 128*j; int r = u >> 3, c = (u & 7) * 4;
        float4 w = make_float4(rna(ax[j].x), rna(ax[j].y), rna(ax[j].z), rna(ax[j].w));
        *(float4*)(As + r*36 + c) = w; }
    #pragma unroll
    for (int j = 0; j < 4; j++) { int u = tid + 128*j; int r = u >> 4, c = (u & 15) * 4;
        float4 w = make_float4(rna(bx[j].x), rna(bx[j].y), rna(bx[j].z), rna(bx[j].w));
        *(float4*)(Bs + r*68 + c) = w; }
    __syncthreads();

    for (int cc = 0; cc < 32; cc++) {
        const int buf = cc & 1;
        if (cc + 1 < 32) {
            const int k0 = (cc + 1) * 32;
            #pragma unroll
            for (int j = 0; j < 8; j++) { int u = tid + 128*j; int r = u >> 3, c = (u & 7) * 4;
                ax[j] = *(const float4*)(x + (size_t)(row0 + r) * CC + k0 + c); }
            #pragma unroll
            for (int j = 0; j < 4; j++) { int u = tid + 128*j; int r = u >> 4, c = (u & 15) * 4;
                bx[j] = *(const float4*)(W + (size_t)(k0 + r) * DKH + c); }
        }
        const float* A = As + buf * (128*36);
        const float* B = Bs + buf * (32*68);
        #pragma unroll
        for (int ks = 0; ks < 4; ks++) {
            uint32_t af[2][4];
            #pragma unroll
            for (int mt = 0; mt < 2; mt++) {
                int r = wid*32 + mt*16 + g;
                af[mt][0] = __float_as_uint(A[r*36       + ks*8 + tg]);
                af[mt][1] = __float_as_uint(A[(r+8)*36   + ks*8 + tg]);
                af[mt][2] = __float_as_uint(A[r*36       + ks*8 + tg + 4]);
                af[mt][3] = __float_as_uint(A[(r+8)*36   + ks*8 + tg + 4]);
            }
            #pragma unroll
            for (int nt = 0; nt < 8; nt++) {
                uint32_t bf[2];
                bf[0] = __float_as_uint(B[(ks*8 + tg)*68     + nt*8 + g]);
                bf[1] = __float_as_uint(B[(ks*8 + tg + 4)*68 + nt*8 + g]);
                mma8(acc[0][nt], af[0], bf);
                mma8(acc[1][nt], af[1], bf);
            }
        }
        if (cc + 1 < 32) {
            float* Ad = As + (buf ^ 1) * (128*36);
            float* Bd = Bs + (buf ^ 1) * (32*68);
            #pragma unroll
            for (int j = 0; j < 8; j++) { int u = tid + 128*j; int r = u >> 3, c = (u & 7) * 4;
                float4 w = make_float4(rna(ax[j].x), rna(ax[j].y), rna(ax[j].z), rna(ax[j].w));
                *(float4*)(Ad + r*36 + c) = w; }
            #pragma unroll
            for (int j = 0; j < 4; j++) { int u = tid + 128*j; int r = u >> 4, c = (u & 15) * 4;
                float4 w = make_float4(rna(bx[j].x), rna(bx[j].y), rna(bx[j].z), rna(bx[j].w));
                *(float4*)(Bd + r*68 + c) = w; }
        }
        __syncthreads();
    }

    // epilogue — pair-permuted writes
    const int yb = blockIdx.y;
    const float sc = (yb == 0) ? 0.125f : 1.0f;
    const int pos0 = pp(2*tg), pos1 = pp(2*tg + 1);
    #pragma unroll
    for (int mt = 0; mt < 2; mt++) {
        const int r = wid*32 + mt*16 + g;
        #pragma unroll
        for (int nt = 0; nt < 8; nt++) {
            float v0 = rna(acc[mt][nt][0]*sc), v1 = rna(acc[mt][nt][1]*sc);
            float v2 = rna(acc[mt][nt][2]*sc), v3 = rna(acc[mt][nt][3]*sc);
            if (yb < 2) {
                // d-dim pair-permuted
                float* dst = (yb == 0) ? g_Q : g_K;
                dst[(size_t)(row0 + r)     * DKH + nt*8 + pos0] = v0;
                dst[(size_t)(row0 + r)     * DKH + nt*8 + pos1] = v1;
                dst[(size_t)(row0 + r + 8) * DKH + nt*8 + pos0] = v2;
                dst[(size_t)(row0 + r + 8) * DKH + nt*8 + pos1] = v3;
            } else {
                // V^T: key-dim pair-permuted (key = token index; cc = g)
                const int gt = row0 + r;
                const int bb = gt >> 11, t0 = gt & 2047;
                const int tp = (t0 & ~7) | pp(g);
                const int col = nt*8 + 2*tg;    // d-dim: original order
                g_Vt[((size_t)bb*DKH + col    ) * TT + tp    ] = v0;
                g_Vt[((size_t)bb*DKH + col + 1) * TT + tp    ] = v1;
                g_Vt[((size_t)bb*DKH + col    ) * TT + tp + 8] = v2;
                g_Vt[((size_t)bb*DKH + col + 1) * TT + tp + 8] = v3;
            }
        }
    }
}

// ---------------------------------------------------------------------------
// Kernel 2: attention.  grid (16, 8), block 256 (8 warps, 16 q-rows each).
// Pair-permuted operands -> every fragment fetch is one LDS.64.
// Row strides 72 (Q/K/P) and 136 (V) keep float2 accesses bank-conflict-free.
// ---------------------------------------------------------------------------
__global__ __launch_bounds__(256) void attn_mma(float* __restrict__ out)
{
    extern __shared__ float sm[];
    float* Qs = sm;                       // [128][72]
    float* Ks = sm + 9216;                // [2][128][72]
    float* Vs = sm + 9216 + 2*9216;       // [2][64][136]
    float* Pp = sm + 27648 + 2*8704;      // [128][72]
    const uint32_t sb = smem_u32(sm);

    const int tid = threadIdx.x, lane = tid & 31, wid = tid >> 5;
    const int g = lane >> 2, tg = lane & 3;
    const int b  = blockIdx.y;
    const int q0 = blockIdx.x * 128;

    const float* Qg = g_Q + ((size_t)b * TT + q0) * DKH;
    const float* Kg = g_K + (size_t)b * TT * DKH;
    const float* Vg = g_Vt + (size_t)b * DKH * TT;

    // prologue: Q + K/V tile 0
    #pragma unroll
    for (int j = 0; j < 8; j++) {
        int u = tid + 256*j;
        int r = u >> 4, c = (u & 15) * 4;                    // 128 x 64
        cpa16(sb + (0    + r*72 + c) * 4, Qg + (size_t)r * DKH + c);
        cpa16(sb + (9216 + r*72 + c) * 4, Kg + (size_t)r * DKH + c);
        int rv = u >> 5, cv = (u & 31) * 4;                  // 64 x 128
        cpa16(sb + (27648 + rv*136 + cv) * 4, Vg + (size_t)rv * TT + cv);
    }
    CP_COMMIT();

    float oacc[8][4];
    #pragma unroll
    for (int nt = 0; nt < 8; nt++)
        #pragma unroll
        for (int i = 0; i < 4; i++) oacc[nt][i] = 0.f;
    float l[2] = {0.f, 0.f};

    const int r = wid*16 + g;   // this thread's q-rows: r and r+8
    const int pos0 = pp(2*tg), pos1 = pp(2*tg + 1);

    for (int t = 0; t < 16; t++) {
        const int buf = t & 1;
        CP_WAIT0();
        __syncthreads();

        if (t + 1 < 16) {    // prefetch next K/V tile
            const int nb = (t + 1) & 1, kt = (t + 1) * 128;
            #pragma unroll
            for (int j = 0; j < 8; j++) {
                int u = tid + 256*j;
                int rr = u >> 4, c = (u & 15) * 4;
                cpa16(sb + (9216 + nb*9216 + rr*72 + c) * 4,
                      Kg + (size_t)(kt + rr) * DKH + c);
                int rv = u >> 5, cv = (u & 31) * 4;
                cpa16(sb + (27648 + nb*8704 + rv*136 + cv) * 4,
                      Vg + (size_t)rv * TT + kt + cv);
            }
            CP_COMMIT();
        }

        const float* K = Ks + buf * 9216;
        const float* V = Vs + buf * 8704;

        #pragma unroll
        for (int h = 0; h < 2; h++) {          // two 64-key halves
            // ---- S = Q * K^T ----
            float sacc[8][4];
            #pragma unroll
            for (int nt = 0; nt < 8; nt++)
                #pragma unroll
                for (int i = 0; i < 4; i++) sacc[nt][i] = 0.f;

            #pragma unroll
            for (int ks = 0; ks < 8; ks++) {
                float2 qa = *(const float2*)(Qs + r*72     + ks*8 + 2*tg);
                float2 qb = *(const float2*)(Qs + (r+8)*72 + ks*8 + 2*tg);
                uint32_t af[4];
                af[0] = __float_as_uint(qa.x); af[2] = __float_as_uint(qa.y);
                af[1] = __float_as_uint(qb.x); af[3] = __float_as_uint(qb.y);
                #pragma unroll
                for (int nt = 0; nt < 8; nt++) {
                    int srow = h*64 + nt*8 + g;
                    float2 kf = *(const float2*)(K + srow*72 + ks*8 + 2*tg);
                    uint32_t bf[2];
                    bf[0] = __float_as_uint(kf.x); bf[1] = __float_as_uint(kf.y);
                    mma8(sacc[nt], af, bf);
                }
            }

            // ---- exp + l + P store (pair-permuted key positions) ----
            #pragma unroll
            for (int nt = 0; nt < 8; nt++) {
                float p0 = rna(__expf(fminf(fmaxf(sacc[nt][0], -60.f), 60.f)));
                float p1 = rna(__expf(fminf(fmaxf(sacc[nt][1], -60.f), 60.f)));
                float p2 = rna(__expf(fminf(fmaxf(sacc[nt][2], -60.f), 60.f)));
                float p3 = rna(__expf(fminf(fmaxf(sacc[nt][3], -60.f), 60.f)));
                l[0] += p0 + p1;
                l[1] += p2 + p3;
                Pp[r*72     + nt*8 + pos0] = p0;
                Pp[r*72     + nt*8 + pos1] = p1;
                Pp[(r+8)*72 + nt*8 + pos0] = p2;
                Pp[(r+8)*72 + nt*8 + pos1] = p3;
            }
            __syncwarp();

            // ---- O += P * V^T ----
            #pragma unroll
            for (int ks = 0; ks < 8; ks++) {
                float2 pa = *(const float2*)(Pp + r*72     + ks*8 + 2*tg);
                float2 pb = *(const float2*)(Pp + (r+8)*72 + ks*8 + 2*tg);
                uint32_t af[4];
                af[0] = __float_as_uint(pa.x); af[2] = __float_as_uint(pa.y);
                af[1] = __float_as_uint(pb.x); af[3] = __float_as_uint(pb.y);
                #pragma unroll
                for (int nt = 0; nt < 8; nt++) {
                    int drow = nt*8 + g;
                    float2 vf = *(const float2*)(V + drow*136 + h*64 + ks*8 + 2*tg);
                    uint32_t bf[2];
                    bf[0] = __float_as_uint(vf.x); bf[1] = __float_as_uint(vf.y);
                    mma8(oacc[nt], af, bf);
                }
            }
            __syncwarp();   // all lanes done reading P before next half rewrites it
        }
    }

    // epilogue: reduce l across the 4-lane tg group, normalize, store
    #pragma unroll
    for (int i = 0; i < 2; i++) {
        l[i] += __shfl_xor_sync(0xffffffffu, l[i], 1);
        l[i] += __shfl_xor_sync(0xffffffffu, l[i], 2);
        l[i] = 1.f / l[i];
    }
    float* og = out + ((size_t)b * TT + q0) * DKH;
    #pragma unroll
    for (int nt = 0; nt < 8; nt++) {
        const int d = nt*8 + 2*tg;     // output d-dim: original order
        *(float2*)(og + (size_t)r * DKH + d) =
            make_float2(oacc[nt][0]*l[0], oacc[nt][1]*l[0]);
        *(float2*)(og + (size_t)(r + 8) * DKH + d) =
            make_float2(oacc[nt][2]*l[1], oacc[nt][3]*l[1]);
    }
}

// ---------------------------------------------------------------------------
extern "C" void kernel_launch(void* const* d_in, const int* in_sizes, int n_in,
                              void* d_out, int out_size)
{
    (void)in_sizes; (void)n_in; (void)out_size;
    const float* x  = (const float*)d_in[0];
    const float* Wq = (const float*)d_in[1];
    const float* Wk = (const float*)d_in[2];
    const float* Wv = (const float*)d_in[3];
    float* out = (float*)d_out;

    const int smem_qkv  = (2*128*36 + 2*32*68) * 4;              // 54,272 B
    const int smem_attn = (9216 + 2*9216 + 2*8704 + 9216) * 4;   // 217,088 B

    cudaFuncSetAttribute(qkv_mma,  cudaFuncAttributeMaxDynamicSharedMemorySize, smem_qkv);
    cudaFuncSetAttribute(attn_mma, cudaFuncAttributeMaxDynamicSharedMemorySize, smem_attn);

    qkv_mma<<<dim3(BT/128, 3), 128, smem_qkv>>>(x, Wq, Wk, Wv);
    attn_mma<<<dim3(TT/128, BB), 256, smem_attn>>>(out);
}

// round 10
// speedup vs baseline: 1.2201x; 1.0424x over previous
#include <cuda_runtime.h>
#include <cstdint>
#include <math.h>

#define BB  8
#define TT  2048
#define CC  1024
#define DKH 64
#define BT  (BB*TT)   // 16384

// tf32-rounded intermediates:
//  g_Q/g_K: d-dim pair-permuted within 8-groups (d -> d<4 ? 2d : 2d-7);
//           Q pre-scaled by dk^-0.5.
//  g_Vt:    [b][d][key], NATURAL key order (PV key-slots are permuted instead).
__device__ __align__(256) float g_Q[BT*DKH];
__device__ __align__(256) float g_K[BT*DKH];
__device__ __align__(256) float g_Vt[BB*DKH*TT];

// ---------------------------------------------------------------------------
// helpers
// ---------------------------------------------------------------------------
__device__ __forceinline__ uint32_t smem_u32(const void* p) {
    uint32_t a;
    asm("{ .reg .u64 t; cvta.to.shared.u64 t, %1; cvt.u32.u64 %0, t; }" : "=r"(a) : "l"(p));
    return a;
}
__device__ __forceinline__ void cpa16(uint32_t s, const void* g) {
    asm volatile("cp.async.cg.shared.global [%0], [%1], 16;" :: "r"(s), "l"(g));
}
#define CP_COMMIT() asm volatile("cp.async.commit_group;" ::: "memory")
#define CP_WAIT0()  asm volatile("cp.async.wait_group 0;"  ::: "memory")

// cvt.rna.tf32.f32 requires a .b32 destination register — "=r", not "=f".
__device__ __forceinline__ float rna(float x) {
    uint32_t y; asm("cvt.rna.tf32.f32 %0, %1;" : "=r"(y) : "f"(x));
    return __uint_as_float(y);
}
// pair-permutation within an 8-group: 0,4,1,5,2,6,3,7
__device__ __forceinline__ int pp(int cc) { return (cc < 4) ? 2*cc : 2*cc - 7; }

// m16n8k8 tf32 mma, D += A*B.  Fragment layout (g = lane>>2, tg = lane&3):
//   a0:(g,k=tg) a1:(g+8,tg) a2:(g,tg+4) a3:(g+8,tg+4)
//   b0:(k=tg,n=g) b1:(k=tg+4,n=g)
//   c0:(g,2tg) c1:(g,2tg+1) c2:(g+8,2tg) c3:(g+8,2tg+1)
__device__ __forceinline__ void mma8(float* d, const uint32_t* a, const uint32_t* b) {
    asm volatile("mma.sync.aligned.m16n8k8.row.col.f32.tf32.tf32.f32 "
        "{%0,%1,%2,%3}, {%4,%5,%6,%7}, {%8,%9}, {%0,%1,%2,%3};"
        : "+f"(d[0]), "+f"(d[1]), "+f"(d[2]), "+f"(d[3])
        : "r"(a[0]), "r"(a[1]), "r"(a[2]), "r"(a[3]), "r"(b[0]), "r"(b[1]));
}

// ---------------------------------------------------------------------------
// Kernel 1: QKV projection.  grid (128, 3), block 128 (4 warps).
// Warp tile 32x64 (2m x 8n).  Q/K written d-pair-permuted; V^T natural keys.
// ---------------------------------------------------------------------------
__global__ __launch_bounds__(128) void qkv_mma(
    const float* __restrict__ x, const float* __restrict__ Wq,
    const float* __restrict__ Wk, const float* __restrict__ Wv)
{
    extern __shared__ float sm[];
    float* As = sm;             // [2][128][36]
    float* Bs = sm + 2*128*36;  // [2][32][68]

    const int tid = threadIdx.x, lane = tid & 31, wid = tid >> 5;
    const int g = lane >> 2, tg = lane & 3;
    const int row0 = blockIdx.x * 128;
    const float* W = (blockIdx.y == 0) ? Wq : (blockIdx.y == 1) ? Wk : Wv;

    float acc[2][8][4];
    #pragma unroll
    for (int mt = 0; mt < 2; mt++)
        #pragma unroll
        for (int nt = 0; nt < 8; nt++)
            #pragma unroll
            for (int i = 0; i < 4; i++) acc[mt][nt][i] = 0.f;

    float4 ax[8], bx[4];
    #pragma unroll
    for (int j = 0; j < 8; j++) { int u = tid + 128*j; int r = u >> 3, c = (u & 7) * 4;
        ax[j] = *(const float4*)(x + (size_t)(row0 + r) * CC + c); }
    #pragma unroll
    for (int j = 0; j < 4; j++) { int u = tid + 128*j; int r = u >> 4, c = (u & 15) * 4;
        bx[j] = *(const float4*)(W + (size_t)r * DKH + c); }
    #pragma unroll
    for (int j = 0; j < 8; j++) { int u = tid + 128*j; int r = u >> 3, c = (u & 7) * 4;
        float4 w = make_float4(rna(ax[j].x), rna(ax[j].y), rna(ax[j].z), rna(ax[j].w));
        *(float4*)(As + r*36 + c) = w; }
    #pragma unroll
    for (int j = 0; j < 4; j++) { int u = tid + 128*j; int r = u >> 4, c = (u & 15) * 4;
        float4 w = make_float4(rna(bx[j].x), rna(bx[j].y), rna(bx[j].z), rna(bx[j].w));
        *(float4*)(Bs + r*68 + c) = w; }
    __syncthreads();

    for (int cc = 0; cc < 32; cc++) {
        const int buf = cc & 1;
        if (cc + 1 < 32) {
            const int k0 = (cc + 1) * 32;
            #pragma unroll
            for (int j = 0; j < 8; j++) { int u = tid + 128*j; int r = u >> 3, c = (u & 7) * 4;
                ax[j] = *(const float4*)(x + (size_t)(row0 + r) * CC + k0 + c); }
            #pragma unroll
            for (int j = 0; j < 4; j++) { int u = tid + 128*j; int r = u >> 4, c = (u & 15) * 4;
                bx[j] = *(const float4*)(W + (size_t)(k0 + r) * DKH + c); }
        }
        const float* A = As + buf * (128*36);
        const float* B = Bs + buf * (32*68);
        #pragma unroll
        for (int ks = 0; ks < 4; ks++) {
            uint32_t af[2][4];
            #pragma unroll
            for (int mt = 0; mt < 2; mt++) {
                int r = wid*32 + mt*16 + g;
                af[mt][0] = __float_as_uint(A[r*36       + ks*8 + tg]);
                af[mt][1] = __float_as_uint(A[(r+8)*36   + ks*8 + tg]);
                af[mt][2] = __float_as_uint(A[r*36       + ks*8 + tg + 4]);
                af[mt][3] = __float_as_uint(A[(r+8)*36   + ks*8 + tg + 4]);
            }
            #pragma unroll
            for (int nt = 0; nt < 8; nt++) {
                uint32_t bf[2];
                bf[0] = __float_as_uint(B[(ks*8 + tg)*68     + nt*8 + g]);
                bf[1] = __float_as_uint(B[(ks*8 + tg + 4)*68 + nt*8 + g]);
                mma8(acc[0][nt], af[0], bf);
                mma8(acc[1][nt], af[1], bf);
            }
        }
        if (cc + 1 < 32) {
            float* Ad = As + (buf ^ 1) * (128*36);
            float* Bd = Bs + (buf ^ 1) * (32*68);
            #pragma unroll
            for (int j = 0; j < 8; j++) { int u = tid + 128*j; int r = u >> 3, c = (u & 7) * 4;
                float4 w = make_float4(rna(ax[j].x), rna(ax[j].y), rna(ax[j].z), rna(ax[j].w));
                *(float4*)(Ad + r*36 + c) = w; }
            #pragma unroll
            for (int j = 0; j < 4; j++) { int u = tid + 128*j; int r = u >> 4, c = (u & 15) * 4;
                float4 w = make_float4(rna(bx[j].x), rna(bx[j].y), rna(bx[j].z), rna(bx[j].w));
                *(float4*)(Bd + r*68 + c) = w; }
        }
        __syncthreads();
    }

    // epilogue
    const int yb = blockIdx.y;
    const float sc = (yb == 0) ? 0.125f : 1.0f;
    const int pos0 = pp(2*tg), pos1 = pp(2*tg + 1);
    #pragma unroll
    for (int mt = 0; mt < 2; mt++) {
        const int r = wid*32 + mt*16 + g;
        #pragma unroll
        for (int nt = 0; nt < 8; nt++) {
            float v0 = rna(acc[mt][nt][0]*sc), v1 = rna(acc[mt][nt][1]*sc);
            float v2 = rna(acc[mt][nt][2]*sc), v3 = rna(acc[mt][nt][3]*sc);
            if (yb < 2) {
                // d-dim pair-permuted
                float* dst = (yb == 0) ? g_Q : g_K;
                dst[(size_t)(row0 + r)     * DKH + nt*8 + pos0] = v0;
                dst[(size_t)(row0 + r)     * DKH + nt*8 + pos1] = v1;
                dst[(size_t)(row0 + r + 8) * DKH + nt*8 + pos0] = v2;
                dst[(size_t)(row0 + r + 8) * DKH + nt*8 + pos1] = v3;
            } else {
                // V^T: natural key order, d natural
                const int gt = row0 + r;
                const int bb = gt >> 11, t0 = gt & 2047;
                const int col = nt*8 + 2*tg;
                g_Vt[((size_t)bb*DKH + col    ) * TT + t0    ] = v0;
                g_Vt[((size_t)bb*DKH + col + 1) * TT + t0    ] = v1;
                g_Vt[((size_t)bb*DKH + col    ) * TT + t0 + 8] = v2;
                g_Vt[((size_t)bb*DKH + col + 1) * TT + t0 + 8] = v3;
            }
        }
    }
}

// ---------------------------------------------------------------------------
// Kernel 2: attention.  grid (16, 8), block 256 (8 warps, 16 q-rows each).
// Q in registers (loaded once).  S accumulator feeds PV directly as the
// A-fragment via key-slot permutation (slot s <-> key pp(s)) — no P smem,
// no intra-tile barriers.  K/V double-buffered via cp.async.
// ---------------------------------------------------------------------------
__global__ __launch_bounds__(256) void attn_mma(float* __restrict__ out)
{
    extern __shared__ float sm[];
    float* Ks = sm;              // [2][128][72]
    float* Vs = sm + 2*9216;     // [2][64][136]
    const uint32_t sb = smem_u32(sm);

    const int tid = threadIdx.x, lane = tid & 31, wid = tid >> 5;
    const int g = lane >> 2, tg = lane & 3;
    const int b  = blockIdx.y;
    const int q0 = blockIdx.x * 128;

    const float* Qg = g_Q + ((size_t)b * TT + q0) * DKH;
    const float* Kg = g_K + (size_t)b * TT * DKH;
    const float* Vg = g_Vt + (size_t)b * DKH * TT;

    const int r = wid*16 + g;   // this thread's q-rows: r and r+8

    // prologue: K/V tile 0 via cp.async
    #pragma unroll
    for (int j = 0; j < 8; j++) {
        int u = tid + 256*j;
        int rr = u >> 4, c = (u & 15) * 4;                   // 128 x 64
        cpa16(sb + (rr*72 + c) * 4, Kg + (size_t)rr * DKH + c);
        int rv = u >> 5, cv = (u & 31) * 4;                  // 64 x 128
        cpa16(sb + (2*9216 + rv*136 + cv) * 4, Vg + (size_t)rv * TT + cv);
    }
    CP_COMMIT();

    // Q fragments in registers (reused across all 16 KV tiles)
    uint32_t qf[8][4];
    #pragma unroll
    for (int ks = 0; ks < 8; ks++) {
        float2 qa = *(const float2*)(Qg + (size_t)r     * DKH + ks*8 + 2*tg);
        float2 qb = *(const float2*)(Qg + (size_t)(r+8) * DKH + ks*8 + 2*tg);
        qf[ks][0] = __float_as_uint(qa.x); qf[ks][2] = __float_as_uint(qa.y);
        qf[ks][1] = __float_as_uint(qb.x); qf[ks][3] = __float_as_uint(qb.y);
    }

    float oacc[8][4];
    #pragma unroll
    for (int nt = 0; nt < 8; nt++)
        #pragma unroll
        for (int i = 0; i < 4; i++) oacc[nt][i] = 0.f;
    float l[2] = {0.f, 0.f};

    for (int t = 0; t < 16; t++) {
        const int buf = t & 1;
        CP_WAIT0();
        __syncthreads();

        if (t + 1 < 16) {    // prefetch next K/V tile
            const int nb = (t + 1) & 1, kt = (t + 1) * 128;
            #pragma unroll
            for (int j = 0; j < 8; j++) {
                int u = tid + 256*j;
                int rr = u >> 4, c = (u & 15) * 4;
                cpa16(sb + (nb*9216 + rr*72 + c) * 4,
                      Kg + (size_t)(kt + rr) * DKH + c);
                int rv = u >> 5, cv = (u & 31) * 4;
                cpa16(sb + (2*9216 + nb*8704 + rv*136 + cv) * 4,
                      Vg + (size_t)rv * TT + kt + cv);
            }
            CP_COMMIT();
        }

        const float* K = Ks + buf * 9216;
        const float* V = Vs + buf * 8704;

        #pragma unroll
        for (int h = 0; h < 2; h++) {          // two 64-key halves
            // ---- S = Q * K^T ----
            float sacc[8][4];
            #pragma unroll
            for (int nt = 0; nt < 8; nt++)
                #pragma unroll
                for (int i = 0; i < 4; i++) sacc[nt][i] = 0.f;

            #pragma unroll
            for (int ks = 0; ks < 8; ks++) {
                #pragma unroll
                for (int nt = 0; nt < 8; nt++) {
                    int srow = h*64 + nt*8 + g;
                    float2 kf = *(const float2*)(K + srow*72 + ks*8 + 2*tg);
                    uint32_t bf[2];
                    bf[0] = __float_as_uint(kf.x); bf[1] = __float_as_uint(kf.y);
                    mma8(sacc[nt], qf[ks], bf);
                }
            }

            // ---- exp then immediately PV, per 8-key group j ----
            // PV contraction slot s corresponds to key pp(s); the S C-fragment
            // is then exactly the PV A-fragment: af = {c0, c2, c1, c3}.
            #pragma unroll
            for (int j = 0; j < 8; j++) {
                float p0 = rna(__expf(fminf(sacc[j][0], 60.f)));
                float p1 = rna(__expf(fminf(sacc[j][1], 60.f)));
                float p2 = rna(__expf(fminf(sacc[j][2], 60.f)));
                float p3 = rna(__expf(fminf(sacc[j][3], 60.f)));
                l[0] += p0 + p1;
                l[1] += p2 + p3;
                uint32_t paf[4];
                paf[0] = __float_as_uint(p0); paf[1] = __float_as_uint(p2);
                paf[2] = __float_as_uint(p1); paf[3] = __float_as_uint(p3);
                #pragma unroll
                for (int nt = 0; nt < 8; nt++) {
                    int drow = nt*8 + g;
                    float2 vf = *(const float2*)(V + drow*136 + h*64 + j*8 + 2*tg);
                    uint32_t bf[2];
                    bf[0] = __float_as_uint(vf.x); bf[1] = __float_as_uint(vf.y);
                    mma8(oacc[nt], paf, bf);
                }
            }
        }
    }

    // epilogue: reduce l across the 4-lane tg group, normalize, store
    #pragma unroll
    for (int i = 0; i < 2; i++) {
        l[i] += __shfl_xor_sync(0xffffffffu, l[i], 1);
        l[i] += __shfl_xor_sync(0xffffffffu, l[i], 2);
        l[i] = 1.f / l[i];
    }
    float* og = out + ((size_t)b * TT + q0) * DKH;
    #pragma unroll
    for (int nt = 0; nt < 8; nt++) {
        const int d = nt*8 + 2*tg;     // output d-dim: original order
        *(float2*)(og + (size_t)r * DKH + d) =
            make_float2(oacc[nt][0]*l[0], oacc[nt][1]*l[0]);
        *(float2*)(og + (size_t)(r + 8) * DKH + d) =
            make_float2(oacc[nt][2]*l[1], oacc[nt][3]*l[1]);
    }
}

// ---------------------------------------------------------------------------
extern "C" void kernel_launch(void* const* d_in, const int* in_sizes, int n_in,
                              void* d_out, int out_size)
{
    (void)in_sizes; (void)n_in; (void)out_size;
    const float* x  = (const float*)d_in[0];
    const float* Wq = (const float*)d_in[1];
    const float* Wk = (const float*)d_in[2];
    const float* Wv = (const float*)d_in[3];
    float* out = (float*)d_out;

    const int smem_qkv  = (2*128*36 + 2*32*68) * 4;     // 54,272 B
    const int smem_attn = (2*9216 + 2*8704) * 4;        // 143,360 B

    cudaFuncSetAttribute(qkv_mma,  cudaFuncAttributeMaxDynamicSharedMemorySize, smem_qkv);
    cudaFuncSetAttribute(attn_mma, cudaFuncAttributeMaxDynamicSharedMemorySize, smem_attn);

    qkv_mma<<<dim3(BT/128, 3), 128, smem_qkv>>>(x, Wq, Wk, Wv);
    attn_mma<<<dim3(TT/128, BB), 256, smem_attn>>>(out);
}

// round 11
// speedup vs baseline: 1.3917x; 1.1407x over previous
#include <cuda_runtime.h>
#include <cstdint>
#include <math.h>

#define BB  8
#define TT  2048
#define CC  1024
#define DKH 64
#define BT  (BB*TT)   // 16384

// tf32-rounded intermediates:
//  g_Q/g_K: d-dim pair-permuted within 8-groups (d -> d<4 ? 2d : 2d-7);
//           Q pre-scaled by dk^-0.5.
//  g_Vt:    [b][d][key], NATURAL key order (PV key-slots are permuted instead).
__device__ __align__(256) float g_Q[BT*DKH];
__device__ __align__(256) float g_K[BT*DKH];
__device__ __align__(256) float g_Vt[BB*DKH*TT];

// ---------------------------------------------------------------------------
// helpers
// ---------------------------------------------------------------------------
__device__ __forceinline__ uint32_t smem_u32(const void* p) {
    uint32_t a;
    asm("{ .reg .u64 t; cvta.to.shared.u64 t, %1; cvt.u32.u64 %0, t; }" : "=r"(a) : "l"(p));
    return a;
}
__device__ __forceinline__ void cpa16(uint32_t s, const void* g) {
    asm volatile("cp.async.cg.shared.global [%0], [%1], 16;" :: "r"(s), "l"(g));
}
#define CP_COMMIT() asm volatile("cp.async.commit_group;" ::: "memory")
#define CP_WAIT0()  asm volatile("cp.async.wait_group 0;"  ::: "memory")

// cvt.rna.tf32.f32 requires a .b32 destination register — "=r", not "=f".
__device__ __forceinline__ float rna(float x) {
    uint32_t y; asm("cvt.rna.tf32.f32 %0, %1;" : "=r"(y) : "f"(x));
    return __uint_as_float(y);
}
// pair-permutation within an 8-group: 0,4,1,5,2,6,3,7
__device__ __forceinline__ int pp(int cc) { return (cc < 4) ? 2*cc : 2*cc - 7; }

// m16n8k8 tf32 mma, D += A*B.  Fragment layout (g = lane>>2, tg = lane&3):
//   a0:(g,k=tg) a1:(g+8,tg) a2:(g,tg+4) a3:(g+8,tg+4)
//   b0:(k=tg,n=g) b1:(k=tg+4,n=g)
//   c0:(g,2tg) c1:(g,2tg+1) c2:(g+8,2tg) c3:(g+8,2tg+1)
__device__ __forceinline__ void mma8(float* d, const uint32_t* a, const uint32_t* b) {
    asm volatile("mma.sync.aligned.m16n8k8.row.col.f32.tf32.tf32.f32 "
        "{%0,%1,%2,%3}, {%4,%5,%6,%7}, {%8,%9}, {%0,%1,%2,%3};"
        : "+f"(d[0]), "+f"(d[1]), "+f"(d[2]), "+f"(d[3])
        : "r"(a[0]), "r"(a[1]), "r"(a[2]), "r"(a[3]), "r"(b[0]), "r"(b[1]));
}

// ---------------------------------------------------------------------------
// Kernel 1: QKV projection.  grid (128, 3), block 128 (4 warps).
// Warp tile 32x64 (2m x 8n).  Q/K written d-pair-permuted; V^T natural keys.
// (unchanged — measured-good config)
// ---------------------------------------------------------------------------
__global__ __launch_bounds__(128) void qkv_mma(
    const float* __restrict__ x, const float* __restrict__ Wq,
    const float* __restrict__ Wk, const float* __restrict__ Wv)
{
    extern __shared__ float sm[];
    float* As = sm;             // [2][128][36]
    float* Bs = sm + 2*128*36;  // [2][32][68]

    const int tid = threadIdx.x, lane = tid & 31, wid = tid >> 5;
    const int g = lane >> 2, tg = lane & 3;
    const int row0 = blockIdx.x * 128;
    const float* W = (blockIdx.y == 0) ? Wq : (blockIdx.y == 1) ? Wk : Wv;

    float acc[2][8][4];
    #pragma unroll
    for (int mt = 0; mt < 2; mt++)
        #pragma unroll
        for (int nt = 0; nt < 8; nt++)
            #pragma unroll
            for (int i = 0; i < 4; i++) acc[mt][nt][i] = 0.f;

    float4 ax[8], bx[4];
    #pragma unroll
    for (int j = 0; j < 8; j++) { int u = tid + 128*j; int r = u >> 3, c = (u & 7) * 4;
        ax[j] = *(const float4*)(x + (size_t)(row0 + r) * CC + c); }
    #pragma unroll
    for (int j = 0; j < 4; j++) { int u = tid + 128*j; int r = u >> 4, c = (u & 15) * 4;
        bx[j] = *(const float4*)(W + (size_t)r * DKH + c); }
    #pragma unroll
    for (int j = 0; j < 8; j++) { int u = tid + 128*j; int r = u >> 3, c = (u & 7) * 4;
        float4 w = make_float4(rna(ax[j].x), rna(ax[j].y), rna(ax[j].z), rna(ax[j].w));
        *(float4*)(As + r*36 + c) = w; }
    #pragma unroll
    for (int j = 0; j < 4; j++) { int u = tid + 128*j; int r = u >> 4, c = (u & 15) * 4;
        float4 w = make_float4(rna(bx[j].x), rna(bx[j].y), rna(bx[j].z), rna(bx[j].w));
        *(float4*)(Bs + r*68 + c) = w; }
    __syncthreads();

    for (int cc = 0; cc < 32; cc++) {
        const int buf = cc & 1;
        if (cc + 1 < 32) {
            const int k0 = (cc + 1) * 32;
            #pragma unroll
            for (int j = 0; j < 8; j++) { int u = tid + 128*j; int r = u >> 3, c = (u & 7) * 4;
                ax[j] = *(const float4*)(x + (size_t)(row0 + r) * CC + k0 + c); }
            #pragma unroll
            for (int j = 0; j < 4; j++) { int u = tid + 128*j; int r = u >> 4, c = (u & 15) * 4;
                bx[j] = *(const float4*)(W + (size_t)(k0 + r) * DKH + c); }
        }
        const float* A = As + buf * (128*36);
        const float* B = Bs + buf * (32*68);
        #pragma unroll
        for (int ks = 0; ks < 4; ks++) {
            uint32_t af[2][4];
            #pragma unroll
            for (int mt = 0; mt < 2; mt++) {
                int r = wid*32 + mt*16 + g;
                af[mt][0] = __float_as_uint(A[r*36       + ks*8 + tg]);
                af[mt][1] = __float_as_uint(A[(r+8)*36   + ks*8 + tg]);
                af[mt][2] = __float_as_uint(A[r*36       + ks*8 + tg + 4]);
                af[mt][3] = __float_as_uint(A[(r+8)*36   + ks*8 + tg + 4]);
            }
            #pragma unroll
            for (int nt = 0; nt < 8; nt++) {
                uint32_t bf[2];
                bf[0] = __float_as_uint(B[(ks*8 + tg)*68     + nt*8 + g]);
                bf[1] = __float_as_uint(B[(ks*8 + tg + 4)*68 + nt*8 + g]);
                mma8(acc[0][nt], af[0], bf);
                mma8(acc[1][nt], af[1], bf);
            }
        }
        if (cc + 1 < 32) {
            float* Ad = As + (buf ^ 1) * (128*36);
            float* Bd = Bs + (buf ^ 1) * (32*68);
            #pragma unroll
            for (int j = 0; j < 8; j++) { int u = tid + 128*j; int r = u >> 3, c = (u & 7) * 4;
                float4 w = make_float4(rna(ax[j].x), rna(ax[j].y), rna(ax[j].z), rna(ax[j].w));
                *(float4*)(Ad + r*36 + c) = w; }
            #pragma unroll
            for (int j = 0; j < 4; j++) { int u = tid + 128*j; int r = u >> 4, c = (u & 15) * 4;
                float4 w = make_float4(rna(bx[j].x), rna(bx[j].y), rna(bx[j].z), rna(bx[j].w));
                *(float4*)(Bd + r*68 + c) = w; }
        }
        __syncthreads();
    }

    // epilogue
    const int yb = blockIdx.y;
    const float sc = (yb == 0) ? 0.125f : 1.0f;
    const int pos0 = pp(2*tg), pos1 = pp(2*tg + 1);
    #pragma unroll
    for (int mt = 0; mt < 2; mt++) {
        const int r = wid*32 + mt*16 + g;
        #pragma unroll
        for (int nt = 0; nt < 8; nt++) {
            float v0 = rna(acc[mt][nt][0]*sc), v1 = rna(acc[mt][nt][1]*sc);
            float v2 = rna(acc[mt][nt][2]*sc), v3 = rna(acc[mt][nt][3]*sc);
            if (yb < 2) {
                float* dst = (yb == 0) ? g_Q : g_K;
                dst[(size_t)(row0 + r)     * DKH + nt*8 + pos0] = v0;
                dst[(size_t)(row0 + r)     * DKH + nt*8 + pos1] = v1;
                dst[(size_t)(row0 + r + 8) * DKH + nt*8 + pos0] = v2;
                dst[(size_t)(row0 + r + 8) * DKH + nt*8 + pos1] = v3;
            } else {
                const int gt = row0 + r;
                const int bb = gt >> 11, t0 = gt & 2047;
                const int col = nt*8 + 2*tg;
                g_Vt[((size_t)bb*DKH + col    ) * TT + t0    ] = v0;
                g_Vt[((size_t)bb*DKH + col + 1) * TT + t0    ] = v1;
                g_Vt[((size_t)bb*DKH + col    ) * TT + t0 + 8] = v2;
                g_Vt[((size_t)bb*DKH + col + 1) * TT + t0 + 8] = v3;
            }
        }
    }
}

// ---------------------------------------------------------------------------
// Kernel 2: attention.  grid (16, 8), block 512 (16 warps).
// Warp w: key-half kw = w>>3 (64 keys of each 128-key tile), q-rows of
// qw = w&7 (rows qw*16+g, +8).  Softmax has no max-subtraction, so partial
// (O, l) over key halves combine ADDITIVELY in a one-time smem bounce.
// Q in registers; S accumulator feeds PV directly (key-slot permutation).
// ---------------------------------------------------------------------------
__global__ __launch_bounds__(512) void attn_mma(float* __restrict__ out)
{
    extern __shared__ float sm[];
    float* Ks = sm;              // [2][128][72]
    float* Vs = sm + 2*9216;     // [2][64][136]
    const uint32_t sb = smem_u32(sm);

    const int tid = threadIdx.x, lane = tid & 31, wid = tid >> 5;
    const int g = lane >> 2, tg = lane & 3;
    const int qw = wid & 7;      // q-row group
    const int kw = wid >> 3;     // key half (0 or 1)
    const int b  = blockIdx.y;
    const int q0 = blockIdx.x * 128;

    const float* Qg = g_Q + ((size_t)b * TT + q0) * DKH;
    const float* Kg = g_K + (size_t)b * TT * DKH;
    const float* Vg = g_Vt + (size_t)b * DKH * TT;

    const int r = qw*16 + g;     // this warp's q-rows: r and r+8

    // prologue: K/V tile 0 via cp.async (512 threads, 4 float4 each per array)
    #pragma unroll
    for (int j = 0; j < 4; j++) {
        int u = tid + 512*j;
        int rr = u >> 4, c = (u & 15) * 4;                   // 128 x 64
        cpa16(sb + (rr*72 + c) * 4, Kg + (size_t)rr * DKH + c);
        int rv = u >> 5, cv = (u & 31) * 4;                  // 64 x 128
        cpa16(sb + (2*9216 + rv*136 + cv) * 4, Vg + (size_t)rv * TT + cv);
    }
    CP_COMMIT();

    // Q fragments in registers (reused across all 16 KV tiles)
    uint32_t qf[8][4];
    #pragma unroll
    for (int ks = 0; ks < 8; ks++) {
        float2 qa = *(const float2*)(Qg + (size_t)r     * DKH + ks*8 + 2*tg);
        float2 qb = *(const float2*)(Qg + (size_t)(r+8) * DKH + ks*8 + 2*tg);
        qf[ks][0] = __float_as_uint(qa.x); qf[ks][2] = __float_as_uint(qa.y);
        qf[ks][1] = __float_as_uint(qb.x); qf[ks][3] = __float_as_uint(qb.y);
    }

    float oacc[8][4];
    #pragma unroll
    for (int nt = 0; nt < 8; nt++)
        #pragma unroll
        for (int i = 0; i < 4; i++) oacc[nt][i] = 0.f;
    float l[2] = {0.f, 0.f};

    for (int t = 0; t < 16; t++) {
        const int buf = t & 1;
        CP_WAIT0();
        __syncthreads();

        if (t + 1 < 16) {    // prefetch next K/V tile
            const int nb = (t + 1) & 1, kt = (t + 1) * 128;
            #pragma unroll
            for (int j = 0; j < 4; j++) {
                int u = tid + 512*j;
                int rr = u >> 4, c = (u & 15) * 4;
                cpa16(sb + (nb*9216 + rr*72 + c) * 4,
                      Kg + (size_t)(kt + rr) * DKH + c);
                int rv = u >> 5, cv = (u & 31) * 4;
                cpa16(sb + (2*9216 + nb*8704 + rv*136 + cv) * 4,
                      Vg + (size_t)rv * TT + kt + cv);
            }
            CP_COMMIT();
        }

        const float* K = Ks + buf * 9216;
        const float* V = Vs + buf * 8704;

        // ---- S = Q * K^T over this warp's 64-key half ----
        float sacc[8][4];
        #pragma unroll
        for (int nt = 0; nt < 8; nt++)
            #pragma unroll
            for (int i = 0; i < 4; i++) sacc[nt][i] = 0.f;

        #pragma unroll
        for (int ks = 0; ks < 8; ks++) {
            #pragma unroll
            for (int nt = 0; nt < 8; nt++) {
                int srow = kw*64 + nt*8 + g;
                float2 kf = *(const float2*)(K + srow*72 + ks*8 + 2*tg);
                uint32_t bf[2];
                bf[0] = __float_as_uint(kf.x); bf[1] = __float_as_uint(kf.y);
                mma8(sacc[nt], qf[ks], bf);
            }
        }

        // ---- exp then immediately PV, per 8-key group j ----
        // PV contraction slot s corresponds to key pp(s); the S C-fragment
        // is then exactly the PV A-fragment: af = {c0, c2, c1, c3}.
        #pragma unroll
        for (int j = 0; j < 8; j++) {
            float p0 = rna(__expf(fminf(sacc[j][0], 60.f)));
            float p1 = rna(__expf(fminf(sacc[j][1], 60.f)));
            float p2 = rna(__expf(fminf(sacc[j][2], 60.f)));
            float p3 = rna(__expf(fminf(sacc[j][3], 60.f)));
            l[0] += p0 + p1;
            l[1] += p2 + p3;
            uint32_t paf[4];
            paf[0] = __float_as_uint(p0); paf[1] = __float_as_uint(p2);
            paf[2] = __float_as_uint(p1); paf[3] = __float_as_uint(p3);
            #pragma unroll
            for (int nt = 0; nt < 8; nt++) {
                int drow = nt*8 + g;
                float2 vf = *(const float2*)(V + drow*136 + kw*64 + j*8 + 2*tg);
                uint32_t bf[2];
                bf[0] = __float_as_uint(vf.x); bf[1] = __float_as_uint(vf.y);
                mma8(oacc[nt], paf, bf);
            }
        }
    }

    // ---- combine the two key-half partials (additive) via smem bounce ----
    __syncthreads();                 // all warps done reading K/V buffers
    float* scr = sm;                 // reuse K buffer: 256 threads x 34 floats
    const int base = (qw*32 + lane) * 34;
    if (kw == 1) {
        #pragma unroll
        for (int nt = 0; nt < 8; nt++) {
            scr[base + nt*4 + 0] = oacc[nt][0];
            scr[base + nt*4 + 1] = oacc[nt][1];
            scr[base + nt*4 + 2] = oacc[nt][2];
            scr[base + nt*4 + 3] = oacc[nt][3];
        }
        scr[base + 32] = l[0];
        scr[base + 33] = l[1];
    }
    __syncthreads();
    if (kw == 0) {
        #pragma unroll
        for (int nt = 0; nt < 8; nt++) {
            oacc[nt][0] += scr[base + nt*4 + 0];
            oacc[nt][1] += scr[base + nt*4 + 1];
            oacc[nt][2] += scr[base + nt*4 + 2];
            oacc[nt][3] += scr[base + nt*4 + 3];
        }
        l[0] += scr[base + 32];
        l[1] += scr[base + 33];

        // reduce l across the 4-lane tg group, normalize, store
        #pragma unroll
        for (int i = 0; i < 2; i++) {
            l[i] += __shfl_xor_sync(0xffffffffu, l[i], 1);
            l[i] += __shfl_xor_sync(0xffffffffu, l[i], 2);
            l[i] = 1.f / l[i];
        }
        float* og = out + ((size_t)b * TT + q0) * DKH;
        #pragma unroll
        for (int nt = 0; nt < 8; nt++) {
            const int d = nt*8 + 2*tg;     // output d-dim: original order
            *(float2*)(og + (size_t)r * DKH + d) =
                make_float2(oacc[nt][0]*l[0], oacc[nt][1]*l[0]);
            *(float2*)(og + (size_t)(r + 8) * DKH + d) =
                make_float2(oacc[nt][2]*l[1], oacc[nt][3]*l[1]);
        }
    }
}

// ---------------------------------------------------------------------------
extern "C" void kernel_launch(void* const* d_in, const int* in_sizes, int n_in,
                              void* d_out, int out_size)
{
    (void)in_sizes; (void)n_in; (void)out_size;
    const float* x  = (const float*)d_in[0];
    const float* Wq = (const float*)d_in[1];
    const float* Wk = (const float*)d_in[2];
    const float* Wv = (const float*)d_in[3];
    float* out = (float*)d_out;

    const int smem_qkv  = (2*128*36 + 2*32*68) * 4;     // 54,272 B
    const int smem_attn = (2*9216 + 2*8704) * 4;        // 143,360 B

    cudaFuncSetAttribute(qkv_mma,  cudaFuncAttributeMaxDynamicSharedMemorySize, smem_qkv);
    cudaFuncSetAttribute(attn_mma, cudaFuncAttributeMaxDynamicSharedMemorySize, smem_attn);

    qkv_mma<<<dim3(BT/128, 3), 128, smem_qkv>>>(x, Wq, Wk, Wv);
    attn_mma<<<dim3(TT/128, BB), 512, smem_attn>>>(out);
}

// round 13
// speedup vs baseline: 1.9864x; 1.4273x over previous
#include <cuda_runtime.h>
#include <cuda_fp16.h>
#include <cstdint>
#include <math.h>

#define BB  8
#define TT  2048
#define CC  1024
#define DKH 64
#define BT  (BB*TT)   // 16384

// fp16 intermediates, NATURAL layouts (m16n8k16 fragments use adjacent pairs):
//  g_Q/g_K: [token][d], Q pre-scaled by dk^-0.5
//  g_Vt:    [b][d][key]
//  g_Wt:    [wsel][d][k]  (transposed weights, prepass)
__device__ __align__(256) __half g_Q[BT*DKH];
__device__ __align__(256) __half g_K[BT*DKH];
__device__ __align__(256) __half g_Vt[BB*DKH*TT];
__device__ __align__(256) __half g_Wt[3*DKH*CC];

// ---------------------------------------------------------------------------
// helpers
// ---------------------------------------------------------------------------
__device__ __forceinline__ uint32_t smem_u32(const void* p) {
    uint32_t a;
    asm("{ .reg .u64 t; cvta.to.shared.u64 t, %1; cvt.u32.u64 %0, t; }" : "=r"(a) : "l"(p));
    return a;
}
__device__ __forceinline__ void cpa16(uint32_t s, const void* g) {
    asm volatile("cp.async.cg.shared.global [%0], [%1], 16;" :: "r"(s), "l"(g));
}
#define CP_COMMIT() asm volatile("cp.async.commit_group;" ::: "memory")
#define CP_WAIT0()  asm volatile("cp.async.wait_group 0;"  ::: "memory")

// pack two f32 -> f16x2 (lo = first arg = low half, matching memory order)
__device__ __forceinline__ uint32_t h2pack(float lo, float hi) {
    __half2 h = __floats2half2_rn(lo, hi);
    return *(uint32_t*)&h;
}

// m16n8k16 fp16 mma, fp32 accum.  Fragment layout (g = lane>>2, tg = lane&3):
//   a0:{(g,2tg),(g,2tg+1)} a1:{(g+8,2tg),(g+8,2tg+1)}
//   a2:{(g,2tg+8),(g,2tg+9)} a3:{(g+8,2tg+8),(g+8,2tg+9)}
//   b0:{(k=2tg,n=g),(2tg+1,g)} b1:{(2tg+8,g),(2tg+9,g)}
//   c0:(g,2tg) c1:(g,2tg+1) c2:(g+8,2tg) c3:(g+8,2tg+1)
__device__ __forceinline__ void mma16(float* d, const uint32_t* a, const uint32_t* b) {
    asm volatile("mma.sync.aligned.m16n8k16.row.col.f32.f16.f16.f32 "
        "{%0,%1,%2,%3}, {%4,%5,%6,%7}, {%8,%9}, {%0,%1,%2,%3};"
        : "+f"(d[0]), "+f"(d[1]), "+f"(d[2]), "+f"(d[3])
        : "r"(a[0]), "r"(a[1]), "r"(a[2]), "r"(a[3]), "r"(b[0]), "r"(b[1]));
}

// ---------------------------------------------------------------------------
// Kernel 0: transpose + convert weights -> g_Wt[wsel][d][k] fp16.
// grid (3, 16), block 256.  768 KB total — microseconds.
// ---------------------------------------------------------------------------
__global__ void wt_kernel(const float* __restrict__ Wq,
                          const float* __restrict__ Wk,
                          const float* __restrict__ Wv)
{
    const float* W = (blockIdx.x == 0) ? Wq : (blockIdx.x == 1) ? Wk : Wv;
    __half* dst = g_Wt + (size_t)blockIdx.x * DKH * CC;
    int u = blockIdx.y * 256 + threadIdx.x;       // 0..4095
    int d  = u >> 6;                              // 0..63
    int k0 = (u & 63) * 16;                       // 0..1008
    #pragma unroll
    for (int j = 0; j < 16; j++) {
        int k = k0 + j;
        dst[d * CC + k] = __float2half_rn(W[(size_t)k * DKH + d]);
    }
}

// ---------------------------------------------------------------------------
// Kernel 1: QKV projection (fp16 mma).  grid (128, 3), block 128 (4 warps).
// Warp tile 32x64; chunk k=32 (2 k16 steps).  x staged LDG->cvt->STS
// (double buffer); W tiles cp.async'd from g_Wt.  Outputs fp16.
// ---------------------------------------------------------------------------
__global__ __launch_bounds__(128) void qkv_mma(const float* __restrict__ x)
{
    extern __shared__ __half smh[];
    __half* As = smh;                 // [2][128][40]
    __half* Bs = smh + 2*5120;        // [2][64][40]
    const uint32_t sb = smem_u32(smh);
    const uint32_t BS_B = 2*5120*2;   // byte offset of Bs

    const int tid = threadIdx.x, lane = tid & 31, wid = tid >> 5;
    const int g = lane >> 2, tg = lane & 3;
    const int row0 = blockIdx.x * 128;
    const int yb = blockIdx.y;
    const __half* Wt = g_Wt + (size_t)yb * DKH * CC;

    float acc[2][8][4];
    #pragma unroll
    for (int mt = 0; mt < 2; mt++)
        #pragma unroll
        for (int nt = 0; nt < 8; nt++)
            #pragma unroll
            for (int i = 0; i < 4; i++) acc[mt][nt][i] = 0.f;

    // prologue: chunk 0.  Bs chunk = 64 rows x 32 halfs = 256 x 16B
    #pragma unroll
    for (int j = 0; j < 2; j++) {
        int e = tid + 128*j;                  // 0..255
        int n = e >> 2, hq = (e & 3) * 8;     // 4 chunks of 8 halfs per row
        cpa16(sb + BS_B + (n*40 + hq)*2, Wt + (size_t)n * CC + hq);
    }
    CP_COMMIT();
    float4 ax[8];
    #pragma unroll
    for (int j = 0; j < 8; j++) { int u = tid + 128*j; int r = u >> 3, c = (u & 7) * 4;
        ax[j] = *(const float4*)(x + (size_t)(row0 + r) * CC + c); }
    #pragma unroll
    for (int j = 0; j < 8; j++) { int u = tid + 128*j; int r = u >> 3, c = (u & 7) * 4;
        uint2 w = make_uint2(h2pack(ax[j].x, ax[j].y), h2pack(ax[j].z, ax[j].w));
        *(uint2*)(As + r*40 + c) = w; }
    CP_WAIT0();
    __syncthreads();

    for (int cc = 0; cc < 32; cc++) {
        const int buf = cc & 1;
        if (cc + 1 < 32) {                 // prefetch next chunk
            const int k0 = (cc + 1) * 32;
            #pragma unroll
            for (int j = 0; j < 2; j++) {
                int e = tid + 128*j;
                int n = e >> 2, hq = (e & 3) * 8;
                cpa16(sb + BS_B + ((buf^1)*2560 + n*40 + hq)*2,
                      Wt + (size_t)n * CC + k0 + hq);
            }
            CP_COMMIT();
            #pragma unroll
            for (int j = 0; j < 8; j++) { int u = tid + 128*j; int r = u >> 3, c = (u & 7) * 4;
                ax[j] = *(const float4*)(x + (size_t)(row0 + r) * CC + k0 + c); }
        }
        const __half* A = As + buf * 5120;
        const __half* B = Bs + buf * 2560;
        #pragma unroll
        for (int s = 0; s < 2; s++) {
            uint32_t af[2][4];
            #pragma unroll
            for (int mt = 0; mt < 2; mt++) {
                int r = wid*32 + mt*16 + g;
                af[mt][0] = *(const uint32_t*)(A + r*40     + s*16 + 2*tg);
                af[mt][1] = *(const uint32_t*)(A + (r+8)*40 + s*16 + 2*tg);
                af[mt][2] = *(const uint32_t*)(A + r*40     + s*16 + 2*tg + 8);
                af[mt][3] = *(const uint32_t*)(A + (r+8)*40 + s*16 + 2*tg + 8);
            }
            #pragma unroll
            for (int nt = 0; nt < 8; nt++) {
                uint32_t bf[2];
                bf[0] = *(const uint32_t*)(B + (nt*8+g)*40 + s*16 + 2*tg);
                bf[1] = *(const uint32_t*)(B + (nt*8+g)*40 + s*16 + 2*tg + 8);
                mma16(acc[0][nt], af[0], bf);
                mma16(acc[1][nt], af[1], bf);
            }
        }
        if (cc + 1 < 32) {                 // store staged x into other buffer
            __half* Ad = As + (buf ^ 1) * 5120;
            #pragma unroll
            for (int j = 0; j < 8; j++) { int u = tid + 128*j; int r = u >> 3, c = (u & 7) * 4;
                uint2 w = make_uint2(h2pack(ax[j].x, ax[j].y), h2pack(ax[j].z, ax[j].w));
                *(uint2*)(Ad + r*40 + c) = w; }
        }
        CP_WAIT0();
        __syncthreads();
    }

    // epilogue
    const float sc = (yb == 0) ? 0.125f : 1.0f;
    #pragma unroll
    for (int mt = 0; mt < 2; mt++) {
        const int r = wid*32 + mt*16 + g;
        #pragma unroll
        for (int nt = 0; nt < 8; nt++) {
            const int col = nt*8 + 2*tg;
            float v0 = acc[mt][nt][0]*sc, v1 = acc[mt][nt][1]*sc;
            float v2 = acc[mt][nt][2]*sc, v3 = acc[mt][nt][3]*sc;
            if (yb < 2) {
                __half* dst = (yb == 0) ? g_Q : g_K;
                *(uint32_t*)(dst + (size_t)(row0 + r)     * DKH + col) = h2pack(v0, v1);
                *(uint32_t*)(dst + (size_t)(row0 + r + 8) * DKH + col) = h2pack(v2, v3);
            } else {
                const int gt = row0 + r;
                const int bb = gt >> 11, t0 = gt & 2047;
                g_Vt[((size_t)bb*DKH + col    ) * TT + t0    ] = __float2half_rn(v0);
                g_Vt[((size_t)bb*DKH + col + 1) * TT + t0    ] = __float2half_rn(v1);
                g_Vt[((size_t)bb*DKH + col    ) * TT + t0 + 8] = __float2half_rn(v2);
                g_Vt[((size_t)bb*DKH + col + 1) * TT + t0 + 8] = __float2half_rn(v3);
            }
        }
    }
}

// ---------------------------------------------------------------------------
// Kernel 2: attention (fp16 mma).  grid (16, 8), block 512 (16 warps).
// Warp w: key-half kw = w>>3, q-rows of qw = w&7.  Q fragments in registers;
// S accumulator feeds PV directly via cvt+pack (no P smem, no intra-tile
// barriers).  Partial (O, l) over key halves combine additively at the end.
// ---------------------------------------------------------------------------
__global__ __launch_bounds__(512) void attn_mma(float* __restrict__ out)
{
    extern __shared__ __half smh[];
    __half* Ks = smh;                 // [2][128][72]
    __half* Vs = smh + 2*9216;        // [2][64][136]
    const uint32_t sb = smem_u32(smh);
    const uint32_t VS_B = 2*9216*2;

    const int tid = threadIdx.x, lane = tid & 31, wid = tid >> 5;
    const int g = lane >> 2, tg = lane & 3;
    const int qw = wid & 7;           // q-row group
    const int kw = wid >> 3;          // key half (0 or 1)
    const int b  = blockIdx.y;
    const int q0 = blockIdx.x * 128;

    const __half* Qg = g_Q + ((size_t)b * TT + q0) * DKH;
    const __half* Kg = g_K + (size_t)b * TT * DKH;
    const __half* Vg = g_Vt + (size_t)b * DKH * TT;

    const int r = qw*16 + g;          // this warp's q-rows: r and r+8

    // prologue: K/V tile 0 via cp.async.
    // K tile: 128 rows x 64 halfs = 1024 x 16B chunks -> row = u>>3, off (u&7)*8
    // V tile: 64 rows x 128 halfs = 1024 x 16B chunks -> row = u>>4, off (u&15)*8
    #pragma unroll
    for (int j = 0; j < 2; j++) {
        int u = tid + 512*j;                          // 0..1023
        int rk = u >> 3, hk = (u & 7) * 8;
        cpa16(sb + (rk*72 + hk)*2, Kg + (size_t)rk * DKH + hk);
        int rv = u >> 4, hv = (u & 15) * 8;
        cpa16(sb + VS_B + (rv*136 + hv)*2, Vg + (size_t)rv * TT + hv);
    }
    CP_COMMIT();

    // Q fragments (4 k16 steps x 4 regs), reused across all tiles
    uint32_t qf[4][4];
    #pragma unroll
    for (int s = 0; s < 4; s++) {
        qf[s][0] = *(const uint32_t*)(Qg + (size_t)r     * DKH + s*16 + 2*tg);
        qf[s][1] = *(const uint32_t*)(Qg + (size_t)(r+8) * DKH + s*16 + 2*tg);
        qf[s][2] = *(const uint32_t*)(Qg + (size_t)r     * DKH + s*16 + 2*tg + 8);
        qf[s][3] = *(const uint32_t*)(Qg + (size_t)(r+8) * DKH + s*16 + 2*tg + 8);
    }

    float oacc[8][4];
    #pragma unroll
    for (int nt = 0; nt < 8; nt++)
        #pragma unroll
        for (int i = 0; i < 4; i++) oacc[nt][i] = 0.f;
    float l[2] = {0.f, 0.f};

    for (int t = 0; t < 16; t++) {
        const int buf = t & 1;
        CP_WAIT0();
        __syncthreads();

        if (t + 1 < 16) {    // prefetch next K/V tile
            const int nb = (t + 1) & 1, kt = (t + 1) * 128;
            #pragma unroll
            for (int j = 0; j < 2; j++) {
                int u = tid + 512*j;
                int rk = u >> 3, hk = (u & 7) * 8;
                cpa16(sb + (nb*9216 + rk*72 + hk)*2,
                      Kg + (size_t)(kt + rk) * DKH + hk);
                int rv = u >> 4, hv = (u & 15) * 8;
                cpa16(sb + VS_B + (nb*8704 + rv*136 + hv)*2,
                      Vg + (size_t)rv * TT + kt + hv);
            }
            CP_COMMIT();
        }

        const __half* K = Ks + buf * 9216;
        const __half* V = Vs + buf * 8704;

        // ---- S = Q * K^T over this warp's 64-key half ----
        float sacc[8][4];
        #pragma unroll
        for (int nt = 0; nt < 8; nt++)
            #pragma unroll
            for (int i = 0; i < 4; i++) sacc[nt][i] = 0.f;

        #pragma unroll
        for (int s = 0; s < 4; s++) {
            #pragma unroll
            for (int nt = 0; nt < 8; nt++) {
                int srow = kw*64 + nt*8 + g;
                uint32_t bf[2];
                bf[0] = *(const uint32_t*)(K + srow*72 + s*16 + 2*tg);
                bf[1] = *(const uint32_t*)(K + srow*72 + s*16 + 2*tg + 8);
                mma16(sacc[nt], qf[s], bf);
            }
        }

        // ---- exp then immediately PV per 16-key group j ----
        // PV A-frag = packed fp16 of the S C-fragments of nt = 2j, 2j+1.
        #pragma unroll
        for (int j = 0; j < 4; j++) {
            float pa0 = __expf(fminf(sacc[2*j][0],   11.f));
            float pa1 = __expf(fminf(sacc[2*j][1],   11.f));
            float pa2 = __expf(fminf(sacc[2*j][2],   11.f));
            float pa3 = __expf(fminf(sacc[2*j][3],   11.f));
            float pb0 = __expf(fminf(sacc[2*j+1][0], 11.f));
            float pb1 = __expf(fminf(sacc[2*j+1][1], 11.f));
            float pb2 = __expf(fminf(sacc[2*j+1][2], 11.f));
            float pb3 = __expf(fminf(sacc[2*j+1][3], 11.f));
            l[0] += pa0 + pa1 + pb0 + pb1;     // row r
            l[1] += pa2 + pa3 + pb2 + pb3;     // row r+8
            uint32_t paf[4];
            paf[0] = h2pack(pa0, pa1);
            paf[1] = h2pack(pa2, pa3);
            paf[2] = h2pack(pb0, pb1);
            paf[3] = h2pack(pb2, pb3);
            const int kb = kw*64 + j*16;
            #pragma unroll
            for (int nt = 0; nt < 8; nt++) {
                int drow = nt*8 + g;
                uint32_t bf[2];
                bf[0] = *(const uint32_t*)(V + drow*136 + kb + 2*tg);
                bf[1] = *(const uint32_t*)(V + drow*136 + kb + 2*tg + 8);
                mma16(oacc[nt], paf, bf);
            }
        }
    }

    // ---- combine the two key-half partials (additive) via smem bounce ----
    __syncthreads();                 // all warps done reading K/V buffers
    float* scr = (float*)smh;        // 256 threads x 34 floats = 34.8 KB
    const int base = (qw*32 + lane) * 34;
    if (kw == 1) {
        #pragma unroll
        for (int nt = 0; nt < 8; nt++) {
            scr[base + nt*4 + 0] = oacc[nt][0];
            scr[base + nt*4 + 1] = oacc[nt][1];
            scr[base + nt*4 + 2] = oacc[nt][2];
            scr[base + nt*4 + 3] = oacc[nt][3];
        }
        scr[base + 32] = l[0];
        scr[base + 33] = l[1];
    }
    __syncthreads();
    if (kw == 0) {
        #pragma unroll
        for (int nt = 0; nt < 8; nt++) {
            oacc[nt][0] += scr[base + nt*4 + 0];
            oacc[nt][1] += scr[base + nt*4 + 1];
            oacc[nt][2] += scr[base + nt*4 + 2];
            oacc[nt][3] += scr[base + nt*4 + 3];
        }
        l[0] += scr[base + 32];
        l[1] += scr[base + 33];

        #pragma unroll
        for (int i = 0; i < 2; i++) {
            l[i] += __shfl_xor_sync(0xffffffffu, l[i], 1);
            l[i] += __shfl_xor_sync(0xffffffffu, l[i], 2);
            l[i] = 1.f / l[i];
        }
        float* og = out + ((size_t)b * TT + q0) * DKH;
        #pragma unroll
        for (int nt = 0; nt < 8; nt++) {
            const int d = nt*8 + 2*tg;
            *(float2*)(og + (size_t)r * DKH + d) =
                make_float2(oacc[nt][0]*l[0], oacc[nt][1]*l[0]);
            *(float2*)(og + (size_t)(r + 8) * DKH + d) =
                make_float2(oacc[nt][2]*l[1], oacc[nt][3]*l[1]);
        }
    }
}

// ---------------------------------------------------------------------------
extern "C" void kernel_launch(void* const* d_in, const int* in_sizes, int n_in,
                              void* d_out, int out_size)
{
    (void)in_sizes; (void)n_in; (void)out_size;
    const float* x  = (const float*)d_in[0];
    const float* Wq = (const float*)d_in[1];
    const float* Wk = (const float*)d_in[2];
    const float* Wv = (const float*)d_in[3];
    float* out = (float*)d_out;

    const int smem_qkv  = (2*5120 + 2*2560) * 2;    // 30,720 B
    const int smem_attn = (2*9216 + 2*8704) * 2;    // 71,680 B

    cudaFuncSetAttribute(qkv_mma,  cudaFuncAttributeMaxDynamicSharedMemorySize, smem_qkv);
    cudaFuncSetAttribute(attn_mma, cudaFuncAttributeMaxDynamicSharedMemorySize, smem_attn);

    wt_kernel<<<dim3(3, 16), 256>>>(Wq, Wk, Wv);
    qkv_mma<<<dim3(BT/128, 3), 128, smem_qkv>>>(x);
    attn_mma<<<dim3(TT/128, BB), 512, smem_attn>>>(out);
}